// round 2
// baseline (speedup 1.0000x reference)
#include <cuda_runtime.h>
#include <math.h>

// Problem constants
#define NFRAMES 16          // B*T = 4*4
#define IMG_H   480
#define IMG_W   640
#define NCH     20          // 4 + NSEM
#define PLANE   (IMG_H * IMG_W)   // 307200
#define DS_H    120         // 480/4
#define DS_W    160         // 640/4
#define NPIX    (DS_H * DS_W)     // 19200
#define VR      100
#define CELLS   (VR * VR)         // 10000
#define NSEM    16
#define NOUT    (2 + NSEM)        // 18
#define MIN_MAPPED 13
#define MAX_MAPPED 25       // exclusive

// Scratch accumulator: [frame][channel][y][x]; ch0=obstacle ind., ch1=explored ind., ch2..17=sem sums
__device__ float g_acc[NFRAMES * NOUT * CELLS];

__global__ void zero_kernel() {
    // 2.88M floats = 720K float4; grid-stride so few blocks, high per-thread work
    const int n4 = NFRAMES * NOUT * CELLS / 4;
    float4* p = (float4*)g_acc;
    const float4 z = make_float4(0.f, 0.f, 0.f, 0.f);
    for (int i = blockIdx.x * blockDim.x + threadIdx.x; i < n4; i += gridDim.x * blockDim.x)
        p[i] = z;
}

__global__ void scatter_kernel(const float* __restrict__ obs, float f_pix) {
    int idx = blockIdx.x * blockDim.x + threadIdx.x;
    if (idx >= NFRAMES * NPIX) return;
    int f   = idx / NPIX;
    int pix = idx - f * NPIX;
    int row = pix / DS_W;
    int col = pix - row * DS_W;

    const float* base = obs + (size_t)f * NCH * PLANE;
    int poff = (row * 4) * IMG_W + col * 4;   // strided ::4,::4 sampling

    float depth = __ldg(&base[3 * PLANE + poff]);
    if (!(depth > 20.0f && depth < 500.0f)) return;

    float uu = (float)(col * 4);
    float vv = (float)(row * 4);

    // Match reference op order exactly
    float X  = __fdiv_rn((uu - 320.0f) * depth, f_pix);
    float Zh = 88.0f + __fdiv_rn((240.0f - vv) * depth, f_pix);

    int xb = __float2int_rn(__fdiv_rn(X, 5.0f) + 50.0f);   // round half-even like jnp.round
    int yb = __float2int_rn(__fdiv_rn(depth, 5.0f));
    int zb = __float2int_rn(__fdiv_rn(Zh, 5.0f)) + 8;      // - MIN_VOX (= -8)

    if (xb < 0 || xb >= VR || yb < 0 || yb >= VR || zb < 0 || zb >= 80) return;

    int cell   = yb * VR + xb;
    float* acc = g_acc + (size_t)f * NOUT * CELLS;

    // Batch all 16 semantic loads first (max MLP), then issue atomics
    float s[NSEM];
    #pragma unroll
    for (int c = 0; c < NSEM; c++)
        s[c] = __ldg(&base[(4 + c) * PLANE + poff]);

    // explored: indicator -> idempotent plain store (deterministic)
    acc[CELLS + cell] = 1.0f;
    // obstacle: indicator of any point with zb in [MIN_MAPPED, MAX_MAPPED)
    if (zb >= MIN_MAPPED && zb < MAX_MAPPED)
        acc[cell] = 1.0f;

    #pragma unroll
    for (int c = 0; c < NSEM; c++)
        atomicAdd(&acc[(2 + c) * CELLS + cell], s[c]);
}

__device__ __forceinline__ float acc_at(const float* acc, int y, int x) {
    if (y < 0 || y >= VR || x < 0 || x >= VR) return 0.0f;
    return __ldg(&acc[y * VR + x]);
}

// One thread per 4 consecutive cells (row-aligned since VR=100 is divisible by 4)
__global__ void finalize_kernel(float* __restrict__ out) {
    const int QPF = CELLS / 4;  // 2500 quads per frame
    int idx = blockIdx.x * blockDim.x + threadIdx.x;
    if (idx >= NFRAMES * QPF) return;
    int f = idx / QPF;
    int q = idx - f * QPF;
    int cell0 = q * 4;
    int y  = cell0 / VR;
    int x0 = cell0 - y * VR;

    const float* acc = g_acc + (size_t)f * NOUT * CELLS;
    float* dst       = out   + (size_t)f * NOUT * CELLS;

    // obstacle: 3x3 max dilation for the 4 cells; columns x0-1 .. x0+4
    float c6[3][6];
    #pragma unroll
    for (int r = 0; r < 3; r++) {
        int yy = y - 1 + r;
        #pragma unroll
        for (int j = 0; j < 6; j++)
            c6[r][j] = acc_at(acc, yy, x0 - 1 + j);
    }
    float4 ob;
    {
        float m0, m1, m2, m3;
        m0 = m1 = m2 = m3 = 0.0f;
        #pragma unroll
        for (int r = 0; r < 3; r++) {
            m0 = fmaxf(m0, fmaxf(c6[r][0], fmaxf(c6[r][1], c6[r][2])));
            m1 = fmaxf(m1, fmaxf(c6[r][1], fmaxf(c6[r][2], c6[r][3])));
            m2 = fmaxf(m2, fmaxf(c6[r][2], fmaxf(c6[r][3], c6[r][4])));
            m3 = fmaxf(m3, fmaxf(c6[r][3], fmaxf(c6[r][4], c6[r][5])));
        }
        ob = make_float4(m0, m1, m2, m3);
    }
    *(float4*)(dst + cell0) = ob;

    // explored (EXP_T = 1.0): already an indicator, pass through
    *(float4*)(dst + CELLS + cell0) = *(const float4*)(acc + CELLS + cell0);

    // semantic: clip(sum / 5, 0, 1), vectorized
    #pragma unroll
    for (int c = 0; c < NSEM; c++) {
        float4 v = *(const float4*)(acc + (2 + c) * CELLS + cell0);
        v.x = fminf(fmaxf(__fdiv_rn(v.x, 5.0f), 0.0f), 1.0f);
        v.y = fminf(fmaxf(__fdiv_rn(v.y, 5.0f), 0.0f), 1.0f);
        v.z = fminf(fmaxf(__fdiv_rn(v.z, 5.0f), 0.0f), 1.0f);
        v.w = fminf(fmaxf(__fdiv_rn(v.w, 5.0f), 0.0f), 1.0f);
        *(float4*)(dst + (2 + c) * CELLS + cell0) = v;
    }
}

extern "C" void kernel_launch(void* const* d_in, const int* in_sizes, int n_in,
                              void* d_out, int out_size) {
    const float* obs = (const float*)d_in[0];   // seq_obs: (4,4,20,480,640) f32
    float* out = (float*)d_out;                 // (4,4,18,100,100) f32

    float f_pix = (float)(320.0 / tan(39.5 * 3.14159265358979323846 / 180.0));

    zero_kernel<<<592, 256>>>();
    scatter_kernel<<<(NFRAMES * NPIX + 255) / 256, 256>>>(obs, f_pix);
    finalize_kernel<<<(NFRAMES * (CELLS / 4) + 255) / 256, 256>>>(out);
}

// round 3
// speedup vs baseline: 1.6174x; 1.6174x over previous
#include <cuda_runtime.h>
#include <math.h>

#define NFRAMES 16
#define IMG_H   480
#define IMG_W   640
#define NCH     20
#define PLANE   (IMG_H * IMG_W)
#define DS_H    120
#define DS_W    160
#define NPIX    (DS_H * DS_W)
#define VR      100
#define CELLS   (VR * VR)
#define NSEM    16
#define NOUT    (2 + NSEM)
#define CPC     20          // floats per cell in acc (16 sem + obst + expl + 2 pad)
#define MIN_MAPPED 13
#define MAX_MAPPED 25

// AoS accumulator: per cell 20 floats (5 float4): [0..15]=sem sums, [16]=obstacle-dilated ind,
// [17]=explored ind, [18..19]=pad. float4 type guarantees 16B alignment for red.v4.
// Statically zero-initialized; finalize_kernel restores zeros each launch (invariant).
__device__ float4 g_acc4[NFRAMES * CELLS * (CPC / 4)];

__device__ __forceinline__ void red_v4(float4* addr, float a, float b, float c, float d) {
    asm volatile("red.global.add.v4.f32 [%0], {%1, %2, %3, %4};"
                 :: "l"(addr), "f"(a), "f"(b), "f"(c), "f"(d) : "memory");
}

__global__ void scatter_kernel(const float* __restrict__ obs, float f_pix) {
    int idx = blockIdx.x * blockDim.x + threadIdx.x;
    if (idx >= NFRAMES * NPIX) return;
    int f   = idx / NPIX;
    int pix = idx - f * NPIX;
    int row = pix / DS_W;
    int col = pix - row * DS_W;

    const float* base = obs + (size_t)f * NCH * PLANE;
    int poff = (row * 4) * IMG_W + col * 4;

    float depth = __ldg(&base[3 * PLANE + poff]);
    if (!(depth > 20.0f && depth < 500.0f)) return;

    float uu = (float)(col * 4);
    float vv = (float)(row * 4);

    float X  = __fdiv_rn((uu - 320.0f) * depth, f_pix);
    float Zh = 88.0f + __fdiv_rn((240.0f - vv) * depth, f_pix);

    int xb = __float2int_rn(__fdiv_rn(X, 5.0f) + 50.0f);
    int yb = __float2int_rn(__fdiv_rn(depth, 5.0f));
    int zb = __float2int_rn(__fdiv_rn(Zh, 5.0f)) + 8;

    if (xb < 0 || xb >= VR || yb < 0 || yb >= VR || zb < 0 || zb >= 80) return;

    int cell = yb * VR + xb;
    float* accf  = (float*)g_acc4;
    size_t cbase = ((size_t)f * CELLS + cell) * CPC;

    // Batch all 16 semantic plane loads (max MLP) before the atomics
    float s[NSEM];
    #pragma unroll
    for (int c = 0; c < NSEM; c++)
        s[c] = __ldg(&base[(4 + c) * PLANE + poff]);

    // explored indicator: idempotent plain store
    accf[cbase + 17] = 1.0f;

    // obstacle: write dilated (3x3, clamped) indicator directly — idempotent stores,
    // so finalize never needs neighbor reads and can fuse the acc reset.
    if (zb >= MIN_MAPPED && zb < MAX_MAPPED) {
        int y0 = yb > 0 ? yb - 1 : 0, y1 = yb < VR - 1 ? yb + 1 : VR - 1;
        int x0 = xb > 0 ? xb - 1 : 0, x1 = xb < VR - 1 ? xb + 1 : VR - 1;
        for (int yy = y0; yy <= y1; yy++)
            for (int xx = x0; xx <= x1; xx++)
                accf[((size_t)f * CELLS + yy * VR + xx) * CPC + 16] = 1.0f;
    }

    // 16 semantic adds as 4 vector reductions
    float4* c4 = g_acc4 + ((size_t)f * CELLS + cell) * (CPC / 4);
    red_v4(c4 + 0, s[0],  s[1],  s[2],  s[3]);
    red_v4(c4 + 1, s[4],  s[5],  s[6],  s[7]);
    red_v4(c4 + 2, s[8],  s[9],  s[10], s[11]);
    red_v4(c4 + 3, s[12], s[13], s[14], s[15]);
}

__global__ void finalize_kernel(float* __restrict__ out) {
    int idx = blockIdx.x * blockDim.x + threadIdx.x;
    if (idx >= NFRAMES * CELLS) return;
    int f    = idx / CELLS;
    int cell = idx - f * CELLS;

    float4* c4 = g_acc4 + ((size_t)f * CELLS + cell) * (CPC / 4);
    float4 v0 = c4[0], v1 = c4[1], v2 = c4[2], v3 = c4[3], v4 = c4[4];
    // v4.x = dilated obstacle, v4.y = explored

    float* dst = out + (size_t)f * NOUT * CELLS;
    dst[cell]         = v4.x;   // obstacle (already dilated, already {0,1})
    dst[CELLS + cell] = v4.y;   // explored (EXP_T=1 -> identity)

    float sv[NSEM] = {v0.x,v0.y,v0.z,v0.w, v1.x,v1.y,v1.z,v1.w,
                      v2.x,v2.y,v2.z,v2.w, v3.x,v3.y,v3.z,v3.w};
    #pragma unroll
    for (int c = 0; c < NSEM; c++)
        dst[(2 + c) * CELLS + cell] = fminf(fmaxf(__fdiv_rn(sv[c], 5.0f), 0.0f), 1.0f);

    // Reset this cell's accumulator for the next launch (own cells only -> race-free)
    const float4 z = make_float4(0.f, 0.f, 0.f, 0.f);
    c4[0] = z; c4[1] = z; c4[2] = z; c4[3] = z; c4[4] = z;
}

extern "C" void kernel_launch(void* const* d_in, const int* in_sizes, int n_in,
                              void* d_out, int out_size) {
    const float* obs = (const float*)d_in[0];   // (4,4,20,480,640) f32
    float* out = (float*)d_out;                 // (4,4,18,100,100) f32

    float f_pix = (float)(320.0 / tan(39.5 * 3.14159265358979323846 / 180.0));

    scatter_kernel<<<(NFRAMES * NPIX + 255) / 256, 256>>>(obs, f_pix);
    finalize_kernel<<<(NFRAMES * CELLS + 255) / 256, 256>>>(out);
}

// round 4
// speedup vs baseline: 1.7383x; 1.0748x over previous
#include <cuda_runtime.h>
#include <math.h>

#define NFRAMES 16
#define IMG_H   480
#define IMG_W   640
#define NCH     20
#define PLANE   (IMG_H * IMG_W)
#define DS_H    120
#define DS_W    160
#define NPIX    (DS_H * DS_W)
#define VR      100
#define CELLS   (VR * VR)
#define NSEM    16
#define NOUT    (2 + NSEM)
#define CPC     20          // floats per cell in acc
#define MIN_MAPPED 13
#define MAX_MAPPED 25

// AoS accumulator: per cell 20 floats (5 float4): [0..15]=sem sums, [16]=obstacle-dilated ind,
// [17]=explored ind, [18..19]=pad. Statically zero-initialized; finalize restores zeros.
__device__ float4 g_acc4[NFRAMES * CELLS * (CPC / 4)];

__device__ __forceinline__ void red_v4(float4* addr, float a, float b, float c, float d) {
    asm volatile("red.global.add.v4.f32 [%0], {%1, %2, %3, %4};"
                 :: "l"(addr), "f"(a), "f"(b), "f"(c), "f"(d) : "memory");
}

__global__ void scatter_kernel(const float* __restrict__ obs, float f_pix) {
    int idx = blockIdx.x * blockDim.x + threadIdx.x;
    if (idx >= NFRAMES * NPIX) return;
    int f   = idx / NPIX;
    int pix = idx - f * NPIX;
    int row = pix / DS_W;
    int col = pix - row * DS_W;

    const float* base = obs + (size_t)f * NCH * PLANE;
    int poff = (row * 4) * IMG_W + col * 4;

    float depth = __ldg(&base[3 * PLANE + poff]);
    if (!(depth > 20.0f && depth < 500.0f)) return;

    float uu = (float)(col * 4);
    float vv = (float)(row * 4);

    // Bit-exact binning: keep true divides here (bin flips would be O(1) errors)
    float X  = __fdiv_rn((uu - 320.0f) * depth, f_pix);
    float Zh = 88.0f + __fdiv_rn((240.0f - vv) * depth, f_pix);

    int xb = __float2int_rn(__fdiv_rn(X, 5.0f) + 50.0f);
    int yb = __float2int_rn(__fdiv_rn(depth, 5.0f));
    int zb = __float2int_rn(__fdiv_rn(Zh, 5.0f)) + 8;

    if (xb < 0 || xb >= VR || yb < 0 || yb >= VR || zb < 0 || zb >= 80) return;

    int cell = yb * VR + xb;
    float* accf = (float*)g_acc4;

    // Batch all 16 semantic plane loads (max MLP) before the atomics
    float s[NSEM];
    #pragma unroll
    for (int c = 0; c < NSEM; c++)
        s[c] = __ldg(&base[(4 + c) * PLANE + poff]);

    // explored indicator: idempotent plain store
    accf[((size_t)f * CELLS + cell) * CPC + 17] = 1.0f;

    // obstacle: write dilated (3x3, clamped) indicator directly — idempotent
    if (zb >= MIN_MAPPED && zb < MAX_MAPPED) {
        int y0 = yb > 0 ? yb - 1 : 0, y1 = yb < VR - 1 ? yb + 1 : VR - 1;
        int x0 = xb > 0 ? xb - 1 : 0, x1 = xb < VR - 1 ? xb + 1 : VR - 1;
        for (int yy = y0; yy <= y1; yy++)
            for (int xx = x0; xx <= x1; xx++)
                accf[((size_t)f * CELLS + yy * VR + xx) * CPC + 16] = 1.0f;
    }

    // 16 semantic adds as 4 vector reductions
    float4* c4 = g_acc4 + ((size_t)f * CELLS + cell) * (CPC / 4);
    red_v4(c4 + 0, s[0],  s[1],  s[2],  s[3]);
    red_v4(c4 + 1, s[4],  s[5],  s[6],  s[7]);
    red_v4(c4 + 2, s[8],  s[9],  s[10], s[11]);
    red_v4(c4 + 3, s[12], s[13], s[14], s[15]);
}

__global__ void __launch_bounds__(256) finalize_kernel(float* __restrict__ out) {
    int idx = blockIdx.x * blockDim.x + threadIdx.x;
    if (idx >= NFRAMES * CELLS) return;
    int f    = idx / CELLS;
    int cell = idx - f * CELLS;

    float4* c4 = g_acc4 + ((size_t)f * CELLS + cell) * (CPC / 4);
    float4 v0 = c4[0], v1 = c4[1], v2 = c4[2], v3 = c4[3], v4 = c4[4];

    float* dst = out + (size_t)f * NOUT * CELLS + cell;
    dst[0]     = v4.x;   // obstacle (already dilated, {0,1})
    dst[CELLS] = v4.y;   // explored (EXP_T=1 -> identity)

    float sv[NSEM] = {v0.x,v0.y,v0.z,v0.w, v1.x,v1.y,v1.z,v1.w,
                      v2.x,v2.y,v2.z,v2.w, v3.x,v3.y,v3.z,v3.w};
    float* d = dst + 2 * CELLS;
    #pragma unroll
    for (int c = 0; c < NSEM; c++) {
        // x*0.2f differs from x/5 by <=1 ULP; output-only, far under 1e-3 tol
        d[0] = fminf(fmaxf(__fmul_rn(sv[c], 0.2f), 0.0f), 1.0f);
        d += CELLS;
    }

    // Reset this cell's accumulator for the next launch (own cells only -> race-free)
    const float4 z = make_float4(0.f, 0.f, 0.f, 0.f);
    c4[0] = z; c4[1] = z; c4[2] = z; c4[3] = z; c4[4] = z;
}

extern "C" void kernel_launch(void* const* d_in, const int* in_sizes, int n_in,
                              void* d_out, int out_size) {
    const float* obs = (const float*)d_in[0];   // (4,4,20,480,640) f32
    float* out = (float*)d_out;                 // (4,4,18,100,100) f32

    float f_pix = (float)(320.0 / tan(39.5 * 3.14159265358979323846 / 180.0));

    scatter_kernel<<<(NFRAMES * NPIX + 255) / 256, 256>>>(obs, f_pix);
    finalize_kernel<<<(NFRAMES * CELLS + 255) / 256, 256>>>(out);
}